// round 11
// baseline (speedup 1.0000x reference)
#include <cuda_runtime.h>
#include <math.h>

#define NMAX 100000
#define EMAX 1600000
#define C_IN 64
#define C_OUT 128
#define RPB 64
#define NB_SCAN ((NMAX + 1023) / 1024)

// Scratch (device globals — no allocations allowed)
__device__ float g_y[(size_t)NMAX * C_IN];
__device__ float g_x0[(size_t)NMAX * C_IN];
__device__ float g_x1[(size_t)NMAX * C_IN];
__device__ float g_dinv[NMAX];
__device__ int   g_cnt[NMAX];        // must be 0 at entry of every call (invariant)
__device__ int   g_fillctr[NMAX];    // bump allocators for fill
__device__ int   g_rowstart[NMAX + 1];
__device__ int2  g_edge[EMAX];       // {srcid, coef bits}
__device__ int   g_blocksum[NB_SCAN];
__device__ int   g_flag[NB_SCAN];    // must be 0 at entry (reset by fill_kernel)
__device__ int   g_bar_arrive;       // self-resetting grid barrier
__device__ int   g_bar_depart;

__device__ __forceinline__ int clampi(int v, int lo, int hi) {
    return v < lo ? lo : (v > hi ? hi : v);
}

// ---- f32x2 packed math helpers ----
__device__ __forceinline__ unsigned long long pack2(float lo, float hi) {
    unsigned long long r;
    asm("mov.b64 %0, {%1, %2};" : "=l"(r) : "f"(lo), "f"(hi));
    return r;
}
__device__ __forceinline__ void unpack2(unsigned long long v, float& lo, float& hi) {
    asm("mov.b64 {%0, %1}, %2;" : "=f"(lo), "=f"(hi) : "l"(v));
}
#define FMA_F32X2(d, a, b, c) \
    asm("fma.rn.f32x2 %0, %1, %2, %3;" : "=l"(d) : "l"(a), "l"(b), "l"(c))
#define ADD_F32X2(d, a, b) \
    asm("add.rn.f32x2 %0, %1, %2;" : "=l"(d) : "l"(a), "l"(b))

// self-resetting grid barrier (all nb blocks must be resident)
__device__ __forceinline__ void grid_barrier(int nb) {
    __syncthreads();
    if (threadIdx.x == 0) {
        __threadfence();
        atomicAdd(&g_bar_arrive, 1);
        while (atomicAdd(&g_bar_arrive, 0) < nb) { }
        int d = atomicAdd(&g_bar_depart, 1);
        if (d == nb - 1) {          // last one out resets for the next call
            g_bar_arrive = 0;
            g_bar_depart = 0;
            __threadfence();
        }
    }
    __syncthreads();
}

// ---------------- launch 1: count + scan (fused, persistent) ----------------
__global__ void __launch_bounds__(1024) csr_scan_kernel(
        const int* __restrict__ dst, int e, int n, int nb) {
    // phase 1: degree count (grid-stride)
    for (int i = blockIdx.x * 1024 + threadIdx.x; i < e; i += nb * 1024)
        atomicAdd(&g_cnt[clampi(dst[i], 0, n - 1)], 1);

    grid_barrier(nb);

    // phase 2: block scan + decoupled lookback
    __shared__ int sm[1024];
    __shared__ int prefix_sm;
    const int b = blockIdx.x;
    const int i = b * 1024 + threadIdx.x;

    int v = (i < n) ? g_cnt[i] : 0;
    sm[threadIdx.x] = v;
    __syncthreads();
    #pragma unroll
    for (int off = 1; off < 1024; off <<= 1) {
        int t = (threadIdx.x >= off) ? sm[threadIdx.x - off] : 0;
        __syncthreads();
        sm[threadIdx.x] += t;
        __syncthreads();
    }
    const int total = sm[1023];

    if (threadIdx.x == 0) {
        prefix_sm = 0;
        g_blocksum[b] = total;
        __threadfence();
        atomicExch(&g_flag[b], 1);
    }
    __syncthreads();

    int local = 0;
    for (int p = threadIdx.x; p < b; p += 1024) {
        while (atomicAdd(&g_flag[p], 0) == 0) { }
        local += g_blocksum[p];
    }
    if (local) atomicAdd(&prefix_sm, local);
    __syncthreads();
    const int prefix = prefix_sm;

    if (i < n) {
        int rs = prefix + sm[threadIdx.x] - v;   // exclusive
        g_rowstart[i] = rs;
        g_fillctr[i]  = rs;
        g_dinv[i]     = rsqrtf((float)v + 1.0f);
        g_cnt[i]      = 0;                       // restore invariant
    }
    if (b == nb - 1 && threadIdx.x == 0) g_rowstart[n] = prefix + total;
}

// ---------------- launch 2: fill edges (and reset lookback flags) ---------
__global__ void fill_kernel(const int* __restrict__ src,
                            const int* __restrict__ dst, int e, int n, int nb) {
    int i = blockIdx.x * blockDim.x + threadIdx.x;
    if (i < nb) g_flag[i] = 0;                   // restore invariant
    if (i >= e) return;
    int s = clampi(src[i], 0, n - 1);
    int d = clampi(dst[i], 0, n - 1);
    int pos = atomicAdd(&g_fillctr[d], 1);
    g_edge[pos] = make_int2(s, __float_as_int(g_dinv[s] * g_dinv[d]));
}

// ---------------- aggregate in x-space (64 ch) ----------------
// one warp per node; half-warps process edges t, t+1 in parallel.
__global__ void __launch_bounds__(256)
agg_kernel(const float* __restrict__ xin, int n) {
    int node = (blockIdx.x * blockDim.x + threadIdx.x) >> 5;
    if (node >= n) return;
    int lane = threadIdx.x & 31;
    int half = lane >> 4;
    int hl = lane & 15;

    const float4* x4 = reinterpret_cast<const float4*>(xin);
    float4 acc = make_float4(0.f, 0.f, 0.f, 0.f);

    int e0 = g_rowstart[node];
    int e1 = g_rowstart[node + 1];
    #pragma unroll 4
    for (int t = e0 + half; t < e1; t += 2) {
        int2 ed = __ldg(&g_edge[t]);            // broadcast within half-warp
        float c = __int_as_float(ed.y);
        float4 v = __ldg(&x4[(size_t)ed.x * 16 + hl]);
        acc.x = fmaf(v.x, c, acc.x);
        acc.y = fmaf(v.y, c, acc.y);
        acc.z = fmaf(v.z, c, acc.z);
        acc.w = fmaf(v.w, c, acc.w);
    }
    __syncwarp();
    acc.x += __shfl_xor_sync(0xffffffffu, acc.x, 16);
    acc.y += __shfl_xor_sync(0xffffffffu, acc.y, 16);
    acc.z += __shfl_xor_sync(0xffffffffu, acc.z, 16);
    acc.w += __shfl_xor_sync(0xffffffffu, acc.w, 16);

    if (half == 0) {
        float dv = g_dinv[node], s2 = dv * dv;
        float4 xs = __ldg(&x4[(size_t)node * 16 + hl]);
        acc.x = fmaf(xs.x, s2, acc.x);
        acc.y = fmaf(xs.y, s2, acc.y);
        acc.z = fmaf(xs.z, s2, acc.z);
        acc.w = fmaf(xs.w, s2, acc.w);
        reinterpret_cast<float4*>(g_y)[(size_t)node * 16 + hl] = acc;
    }
}

// ---------------- packed GEMM + bias + GLU + residual ----------------
__global__ void __launch_bounds__(128)
gemm_glu_kernel(const float* __restrict__ xin, float* __restrict__ xout,
                const float* __restrict__ W, const float* __restrict__ b,
                int n) {
    __shared__ unsigned long long ysp[RPB][C_IN];   // 32 KB: pack2(y,y)

    const int j = threadIdx.x;
    const int c = j & 63;
    const int q = j >> 6;
    const int row0 = blockIdx.x * RPB;

    #pragma unroll
    for (int t = j; t < RPB * C_IN; t += 128) {
        int r = t >> 6, k = t & 63;
        int row = row0 + r;
        float v = (row < n) ? g_y[(size_t)row * C_IN + k] : 0.0f;
        ysp[r][k] = pack2(v, v);
    }

    unsigned long long wp[C_IN];
    #pragma unroll
    for (int k = 0; k < C_IN; k++)
        wp[k] = pack2(W[k * C_OUT + c], W[k * C_OUT + c + 64]);
    const unsigned long long bb = pack2(b[c], b[c + 64]);

    __syncthreads();

    #pragma unroll 2
    for (int rr = 0; rr < RPB / 2; rr++) {
        int r = q * (RPB / 2) + rr;
        int row = row0 + r;
        const ulonglong2* yv = reinterpret_cast<const ulonglong2*>(&ysp[r][0]);
        unsigned long long a0 = bb, a1 = 0ull;
        #pragma unroll
        for (int k2 = 0; k2 < 32; k2++) {
            ulonglong2 yy = yv[k2];               // LDS.128 broadcast
            FMA_F32X2(a0, yy.x, wp[2 * k2 + 0], a0);
            FMA_F32X2(a1, yy.y, wp[2 * k2 + 1], a1);
        }
        unsigned long long at;
        ADD_F32X2(at, a0, a1);
        float av, gv;
        unpack2(at, av, gv);
        if (row < n) {
            float sig = 1.0f / (1.0f + expf(-gv));
            xout[(size_t)row * C_IN + c] =
                fmaf(av, sig, xin[(size_t)row * C_IN + c]);
        }
    }
}

extern "C" void kernel_launch(void* const* d_in, const int* in_sizes, int n_in,
                              void* d_out, int out_size) {
    // Identify inputs by SIZE:
    //   x: == out_size (6.4M f32); edge_index: largest rest (3.2M i32);
    //   Ws: next (24576 f32); bs: smallest (384 f32)
    const float* x = nullptr; const float* Ws = nullptr; const float* bs = nullptr;
    const int* ei = nullptr;
    int ei_elems = 0, Ws_elems = 0;
    int used[16] = {0};
    for (int i = 0; i < n_in; i++)
        if (!x && in_sizes[i] == out_size) { x = (const float*)d_in[i]; used[i] = 1; break; }
    {
        int best = -1, bsz = -1;
        for (int i = 0; i < n_in; i++)
            if (!used[i] && in_sizes[i] > bsz) { bsz = in_sizes[i]; best = i; }
        ei = (const int*)d_in[best]; ei_elems = bsz; used[best] = 1;
    }
    {
        int best = -1, bsz = -1;
        for (int i = 0; i < n_in; i++)
            if (!used[i] && in_sizes[i] > bsz) { bsz = in_sizes[i]; best = i; }
        Ws = (const float*)d_in[best]; Ws_elems = bsz; used[best] = 1;
    }
    for (int i = 0; i < n_in; i++)
        if (!used[i]) { bs = (const float*)d_in[i]; used[i] = 1; break; }

    const int n = out_size / C_IN;
    const int e = ei_elems / 2;
    const int L = Ws_elems / (C_IN * C_OUT);
    const int* src = ei;
    const int* dst = ei + e;
    const int nb = (n + 1023) / 1024;   // 98 blocks, all resident

    float *x0, *x1;
    cudaGetSymbolAddress((void**)&x0, g_x0);
    cudaGetSymbolAddress((void**)&x1, g_x1);

    // ---- CSR build: 2 launches ----
    csr_scan_kernel<<<nb, 1024>>>(dst, e, n, nb);               // launch 1
    fill_kernel<<<(e + 255) / 256, 256>>>(src, dst, e, n, nb);  // launch 2

    // ---- layers (gemm of layer 0 is launch 4 -> gets profiled) ----
    const float* xin = x;
    for (int l = 0; l < L; l++) {
        float* xout = (l == L - 1) ? (float*)d_out : ((l & 1) ? x1 : x0);
        agg_kernel<<<(n * 32 + 255) / 256, 256>>>(xin, n);
        gemm_glu_kernel<<<(n + RPB - 1) / RPB, 128>>>(
            xin, xout, Ws + (size_t)l * C_IN * C_OUT, bs + (size_t)l * C_OUT, n);
        xin = xout;
    }
}